// round 15
// baseline (speedup 1.0000x reference)
#include <cuda_runtime.h>

// Problem constants
#define BATCH 8192
#define DIM   512
#define NUM_CLASSES 90
#define KC    8

// One thread per (sample, k) pair: 65536 threads.
#define BLOCKS 128
#define THREADS 512

__device__ float g_terms[BATCH];

__global__ __launch_bounds__(THREADS)
void center_loss_kernel(const float* __restrict__ x,
                        const float* __restrict__ centers,
                        const int* __restrict__ labels) {
    const int gid  = blockIdx.x * THREADS + threadIdx.x;
    const int b    = gid >> 3;          // sample
    const int k    = gid & 7;           // center row within class
    const int lane = threadIdx.x & 31;

    const int lbl = labels[b];          // int32; 8 lanes same addr -> broadcast

    const float4* x4 = reinterpret_cast<const float4*>(x + (size_t)b * DIM);
    const float4* c4 = reinterpret_cast<const float4*>(
        centers + ((size_t)lbl * KC + k) * DIM);

    // LLVM-vectorized fp32 reduce on aarch64 (XLA strength-reduced dot):
    // VF=4, IC=2 -> TWO 4-lane accumulators, fused FMLA.
    // acc0 takes packets 0,2,4,... (elements 8t+0..3), acc1 packets 1,3,5,...
    float4 a0 = make_float4(0.f, 0.f, 0.f, 0.f);
    float4 a1 = make_float4(0.f, 0.f, 0.f, 0.f);
    #pragma unroll 8
    for (int i = 0; i < DIM / 8; i++) {
        const float4 xq0 = x4[2 * i];
        const float4 xq1 = x4[2 * i + 1];
        const float4 cq0 = c4[2 * i];
        const float4 cq1 = c4[2 * i + 1];
        a0.x = fmaf(xq0.x, cq0.x, a0.x);
        a0.y = fmaf(xq0.y, cq0.y, a0.y);
        a0.z = fmaf(xq0.z, cq0.z, a0.z);
        a0.w = fmaf(xq0.w, cq0.w, a0.w);
        a1.x = fmaf(xq1.x, cq1.x, a1.x);
        a1.y = fmaf(xq1.y, cq1.y, a1.y);
        a1.z = fmaf(xq1.z, cq1.z, a1.z);
        a1.w = fmaf(xq1.w, cq1.w, a1.w);
    }

    // Part combine: vector fadd (acc0 + acc1), per lane
    const float s0 = __fadd_rn(a0.x, a1.x);
    const float s1 = __fadd_rn(a0.y, a1.y);
    const float s2 = __fadd_rn(a0.z, a1.z);
    const float s3 = __fadd_rn(a0.w, a1.w);

    // Horizontal: FADDP tree -> (s0+s1) + (s2+s3)
    const float dot = __fadd_rn(__fadd_rn(s0, s1), __fadd_rn(s2, s3));
    const float d = __fadd_rn(1.0f, dot);

    // Gather the 8 d's of this sample in strict k order (group of 8 lanes).
    const int gbase = lane & ~7;
    float dk[KC];
    #pragma unroll
    for (int j = 0; j < KC; j++)
        dk[j] = __shfl_sync(0xffffffffu, d, gbase + j);

    // ssum = d0+...+d7, strict sequential fp32
    float ssum = dk[0];
    #pragma unroll
    for (int j = 1; j < KC; j++) ssum = __fadd_rn(ssum, dk[j]);

    // term = sum_j (d_j/ssum)*d_j, strict sequential, IEEE div, separate mul/add
    float term = __fmul_rn(__fdiv_rn(dk[0], ssum), dk[0]);
    #pragma unroll
    for (int j = 1; j < KC; j++)
        term = __fadd_rn(term, __fmul_rn(__fdiv_rn(dk[j], ssum), dk[j]));

    if (k == 0) g_terms[b] = term;
}

// jnp.mean emulation: strict sequential fp32 chain over b, then /8192.
__global__ void serial_mean_kernel(float* __restrict__ out) {
    if (threadIdx.x == 0) {
        float s = 0.0f;
        #pragma unroll 8
        for (int b = 0; b < BATCH; b++)
            s = __fadd_rn(s, g_terms[b]);
        out[0] = __fdiv_rn(s, (float)BATCH);
    }
}

extern "C" void kernel_launch(void* const* d_in, const int* in_sizes, int n_in,
                              void* d_out, int out_size) {
    const float* x       = (const float*)d_in[0];
    const float* centers = (const float*)d_in[1];
    const int*   labels  = (const int*)d_in[2];
    float* out = (float*)d_out;

    center_loss_kernel<<<BLOCKS, THREADS>>>(x, centers, labels);
    serial_mean_kernel<<<1, 32>>>(out);
}

// round 16
// speedup vs baseline: 4.9700x; 4.9700x over previous
#include <cuda_runtime.h>

// Problem constants
#define BATCH 8192
#define DIM   512
#define NUM_CLASSES 90
#define KC    8

// One thread per (sample, k) pair: 65536 threads.
#define BLOCKS 128
#define THREADS 512
#define WARPS_PER_BLOCK (THREADS / 32)

__device__ double g_partials[BLOCKS];

__global__ __launch_bounds__(THREADS)
void center_loss_kernel(const float* __restrict__ x,
                        const float* __restrict__ centers,
                        const int* __restrict__ labels) {
    const int gid  = blockIdx.x * THREADS + threadIdx.x;
    const int b    = gid >> 3;          // sample
    const int k    = gid & 7;           // center row within class
    const int lane = threadIdx.x & 31;

    const int lbl = labels[b];          // int32; 8 lanes same addr -> broadcast

    const float4* x4 = reinterpret_cast<const float4*>(x + (size_t)b * DIM);
    const float4* c4 = reinterpret_cast<const float4*>(
        centers + ((size_t)lbl * KC + k) * DIM);

    // Reference dot order (verified R15, rel_err 1.47e-5):
    // LLVM-vectorized fp32 reduce, VF=4 IC=2 -> two 4-lane FMA accumulators.
    float4 a0 = make_float4(0.f, 0.f, 0.f, 0.f);
    float4 a1 = make_float4(0.f, 0.f, 0.f, 0.f);
    #pragma unroll 8
    for (int i = 0; i < DIM / 8; i++) {
        const float4 xq0 = x4[2 * i];
        const float4 xq1 = x4[2 * i + 1];
        const float4 cq0 = c4[2 * i];
        const float4 cq1 = c4[2 * i + 1];
        a0.x = fmaf(xq0.x, cq0.x, a0.x);
        a0.y = fmaf(xq0.y, cq0.y, a0.y);
        a0.z = fmaf(xq0.z, cq0.z, a0.z);
        a0.w = fmaf(xq0.w, cq0.w, a0.w);
        a1.x = fmaf(xq1.x, cq1.x, a1.x);
        a1.y = fmaf(xq1.y, cq1.y, a1.y);
        a1.z = fmaf(xq1.z, cq1.z, a1.z);
        a1.w = fmaf(xq1.w, cq1.w, a1.w);
    }

    // Part combine (vector fadd), then FADDP tree: (s0+s1) + (s2+s3)
    const float s0 = __fadd_rn(a0.x, a1.x);
    const float s1 = __fadd_rn(a0.y, a1.y);
    const float s2 = __fadd_rn(a0.z, a1.z);
    const float s3 = __fadd_rn(a0.w, a1.w);
    const float dot = __fadd_rn(__fadd_rn(s0, s1), __fadd_rn(s2, s3));
    const float d = __fadd_rn(1.0f, dot);

    // Gather the 8 d's of this sample in strict k order (group of 8 lanes).
    const int gbase = lane & ~7;
    float dk[KC];
    #pragma unroll
    for (int j = 0; j < KC; j++)
        dk[j] = __shfl_sync(0xffffffffu, d, gbase + j);

    // ssum = d0+...+d7, strict sequential fp32
    float ssum = dk[0];
    #pragma unroll
    for (int j = 1; j < KC; j++) ssum = __fadd_rn(ssum, dk[j]);

    // term = sum_j (d_j/ssum)*d_j, strict sequential, IEEE div, separate mul/add
    float term = __fmul_rn(__fdiv_rn(dk[0], ssum), dk[0]);
    #pragma unroll
    for (int j = 1; j < KC; j++)
        term = __fadd_rn(term, __fmul_rn(__fdiv_rn(dk[j], ssum), dk[j]));

    // Batch mean: deterministic parallel f64 reduction.
    // (Measured R11->R12: mean order contributes only ~1e-5 rel; threshold 1e-3.)
    double t = (k == 0) ? (double)term : 0.0;
    #pragma unroll
    for (int off = 16; off > 0; off >>= 1)
        t += __shfl_xor_sync(0xffffffffu, t, off);

    __shared__ double sh[WARPS_PER_BLOCK];
    const int warp = threadIdx.x >> 5;
    if (lane == 0) sh[warp] = t;
    __syncthreads();
    if (threadIdx.x == 0) {
        double s = 0.0;
        #pragma unroll
        for (int w = 0; w < WARPS_PER_BLOCK; w++) s += sh[w];
        g_partials[blockIdx.x] = s;
    }
}

__global__ void final_reduce_kernel(float* __restrict__ out) {
    __shared__ double sh[BLOCKS];
    sh[threadIdx.x] = g_partials[threadIdx.x];
    __syncthreads();
    #pragma unroll
    for (int off = BLOCKS / 2; off > 0; off >>= 1) {
        if (threadIdx.x < (unsigned)off) sh[threadIdx.x] += sh[threadIdx.x + off];
        __syncthreads();
    }
    if (threadIdx.x == 0) out[0] = (float)(sh[0] / (double)BATCH);
}

extern "C" void kernel_launch(void* const* d_in, const int* in_sizes, int n_in,
                              void* d_out, int out_size) {
    const float* x       = (const float*)d_in[0];
    const float* centers = (const float*)d_in[1];
    const int*   labels  = (const int*)d_in[2];
    float* out = (float*)d_out;

    center_loss_kernel<<<BLOCKS, THREADS>>>(x, centers, labels);
    final_reduce_kernel<<<1, BLOCKS>>>(out);
}

// round 17
// speedup vs baseline: 7.3929x; 1.4875x over previous
#include <cuda_runtime.h>

// Problem constants
#define BATCH 8192
#define DIM   512
#define NUM_CLASSES 90
#define KC    8

// One thread per (sample, k, half): 8192*8*2 = 131072 threads.
// half h=0 runs chain-vector a0 (elements 8t+0..3), h=1 runs a1 (8t+4..7).
#define BLOCKS 256
#define THREADS 512
#define WARPS_PER_BLOCK (THREADS / 32)

__device__ double g_partials[BLOCKS];

__global__ __launch_bounds__(THREADS)
void center_loss_kernel(const float* __restrict__ x,
                        const float* __restrict__ centers,
                        const int* __restrict__ labels) {
    const int gid  = blockIdx.x * THREADS + threadIdx.x;
    const int b    = gid >> 4;          // sample
    const int r    = gid & 15;          // (k, h) within sample
    const int k    = r >> 1;
    const int h    = r & 1;
    const int lane = threadIdx.x & 31;  // warp covers 2 samples (16 lanes each)

    const int lbl = labels[b];          // int32; 16 lanes same addr -> broadcast

    const float4* x4 = reinterpret_cast<const float4*>(x + (size_t)b * DIM);
    const float4* c4 = reinterpret_cast<const float4*>(
        centers + ((size_t)lbl * KC + k) * DIM);

    // One 4-lane FMA chain (half of the verified VF=4 IC=2 structure):
    // h=0: packets 0,2,4,... (a0); h=1: packets 1,3,5,... (a1).
    float4 acc = make_float4(0.f, 0.f, 0.f, 0.f);
    #pragma unroll 8
    for (int t = 0; t < DIM / 8; t++) {
        const float4 xq = x4[2 * t + h];
        const float4 cq = c4[2 * t + h];
        acc.x = fmaf(xq.x, cq.x, acc.x);
        acc.y = fmaf(xq.y, cq.y, acc.y);
        acc.z = fmaf(xq.z, cq.z, acc.z);
        acc.w = fmaf(xq.w, cq.w, acc.w);
    }

    // Part combine a0+a1: exchange with partner lane (h^1) and add per lane.
    // IEEE add is commutative -> both lanes produce identical bits.
    const float p0 = __shfl_xor_sync(0xffffffffu, acc.x, 1);
    const float p1 = __shfl_xor_sync(0xffffffffu, acc.y, 1);
    const float p2 = __shfl_xor_sync(0xffffffffu, acc.z, 1);
    const float p3 = __shfl_xor_sync(0xffffffffu, acc.w, 1);
    const float s0 = __fadd_rn(acc.x, p0);
    const float s1 = __fadd_rn(acc.y, p1);
    const float s2 = __fadd_rn(acc.z, p2);
    const float s3 = __fadd_rn(acc.w, p3);

    // FADDP tree: (s0+s1) + (s2+s3)  (verified order, R15)
    const float dot = __fadd_rn(__fadd_rn(s0, s1), __fadd_rn(s2, s3));
    const float d = __fadd_rn(1.0f, dot);

    // Gather the 8 d's of this sample in strict k order.
    // Sample's lanes start at (lane & 16); k=j lives on lanes base+2j (and +2j+1).
    const int gbase = lane & 16;
    float dk[KC];
    #pragma unroll
    for (int j = 0; j < KC; j++)
        dk[j] = __shfl_sync(0xffffffffu, d, gbase + 2 * j);

    // ssum = d0+...+d7, strict sequential fp32
    float ssum = dk[0];
    #pragma unroll
    for (int j = 1; j < KC; j++) ssum = __fadd_rn(ssum, dk[j]);

    // term = sum_j (d_j/ssum)*d_j, strict sequential, IEEE div, separate mul/add
    float term = __fmul_rn(__fdiv_rn(dk[0], ssum), dk[0]);
    #pragma unroll
    for (int j = 1; j < KC; j++)
        term = __fadd_rn(term, __fmul_rn(__fdiv_rn(dk[j], ssum), dk[j]));

    // Batch mean: deterministic parallel f64 reduction (order-insensitive, measured).
    double t = (r == 0) ? (double)term : 0.0;
    #pragma unroll
    for (int off = 16; off > 0; off >>= 1)
        t += __shfl_xor_sync(0xffffffffu, t, off);

    __shared__ double sh[WARPS_PER_BLOCK];
    const int warp = threadIdx.x >> 5;
    if (lane == 0) sh[warp] = t;
    __syncthreads();
    if (threadIdx.x == 0) {
        double s = 0.0;
        #pragma unroll
        for (int w = 0; w < WARPS_PER_BLOCK; w++) s += sh[w];
        g_partials[blockIdx.x] = s;
    }
}

__global__ void final_reduce_kernel(float* __restrict__ out) {
    __shared__ double sh[BLOCKS];
    sh[threadIdx.x] = g_partials[threadIdx.x];
    __syncthreads();
    #pragma unroll
    for (int off = BLOCKS / 2; off > 0; off >>= 1) {
        if (threadIdx.x < (unsigned)off) sh[threadIdx.x] += sh[threadIdx.x + off];
        __syncthreads();
    }
    if (threadIdx.x == 0) out[0] = (float)(sh[0] / (double)BATCH);
}

extern "C" void kernel_launch(void* const* d_in, const int* in_sizes, int n_in,
                              void* d_out, int out_size) {
    const float* x       = (const float*)d_in[0];
    const float* centers = (const float*)d_in[1];
    const int*   labels  = (const int*)d_in[2];
    float* out = (float*)d_out;

    center_loss_kernel<<<BLOCKS, THREADS>>>(x, centers, labels);
    final_reduce_kernel<<<1, BLOCKS>>>(out);
}